// round 1
// baseline (speedup 1.0000x reference)
#include <cuda_runtime.h>

#define BB 32768
#define LL 35
#define CIN 21
#define FF 128
#define KK 9
#define HH 64
#define NFLANK 10
#define LPAD 48   // 4 zero pad rows front, L=35 real rows (idx 4..38), zeros to 47

typedef unsigned long long ull;

// scratch: conv_result [B][L][F] fp32 (587 MB) — static device allocation (no cudaMalloc)
__device__ float g_conv[(size_t)BB * LL * FF];

__device__ __forceinline__ ull fma2(ull a, ull b, ull c) {
    ull d;
    asm("fma.rn.f32x2 %0, %1, %2, %3;" : "=l"(d) : "l"(a), "l"(b), "l"(c));
    return d;
}
__device__ __forceinline__ ull splat2(float x) {
    ull d;
    asm("mov.b64 %0, {%1, %1};" : "=l"(d) : "f"(x));
    return d;
}
__device__ __forceinline__ float2 asf2(ull v) {
    float2 r;
    asm("mov.b64 {%0, %1}, %2;" : "=f"(r.x), "=f"(r.y) : "l"(v));
    return r;
}

// ---------------------------------------------------------------------------
// Kernel 1: conv1d SAME + bias + relu, two batch elements per block packed in
// f32x2 lanes. smem: full weight tile (9*21*128 f32) + padded seq pair.
// Thread tile: 4 filters x 5 positions x 2 batches = 40 MACs per (k,c) step.
// ---------------------------------------------------------------------------
#define CONV_SMEM (KK*CIN*FF*4 + LPAD*CIN*8)

__global__ void __launch_bounds__(256, 2) conv_kernel(
    const float* __restrict__ seq,
    const float* __restrict__ conv_w,
    const float* __restrict__ conv_b)
{
    extern __shared__ float smem[];
    float* s_w  = smem;                        // 24192 floats
    ull*   s_seq = (ull*)(smem + KK*CIN*FF);   // LPAD*CIN float2 (batch pair)

    const int t  = threadIdx.x;
    const int b0 = blockIdx.x * 2;

    for (int i = t; i < (KK*CIN*FF)/4; i += 256)
        ((float4*)s_w)[i] = ((const float4*)conv_w)[i];

    const float* sA = seq + (size_t)b0 * (LL*CIN);
    const float* sB = sA + LL*CIN;
    for (int i = t; i < LPAD*CIN; i += 256) {
        int row = i / CIN;
        int c   = i - row*CIN;
        int l   = row - 4;
        float2 v = make_float2(0.f, 0.f);
        if (l >= 0 && l < LL) { v.x = sA[l*CIN + c]; v.y = sB[l*CIN + c]; }
        ((float2*)s_seq)[i] = v;
    }
    __syncthreads();

    const int fq = t & 31;     // filter quad
    const int lw = t >> 5;     // 0..7 -> positions lw, lw+8, ... lw+32
    const int f0 = fq * 4;

    ull acc[5][4];
    #pragma unroll
    for (int j = 0; j < 5; ++j)
        #pragma unroll
        for (int i = 0; i < 4; ++i) acc[j][i] = 0ull;

    #pragma unroll 1
    for (int k = 0; k < KK; ++k) {
        #pragma unroll 7
        for (int c = 0; c < CIN; ++c) {
            float4 w4 = *(const float4*)(s_w + (k*CIN + c)*FF + f0);
            ull w0 = splat2(w4.x), w1 = splat2(w4.y);
            ull w2 = splat2(w4.z), w3 = splat2(w4.w);
            int base = (lw + k)*CIN + c;   // padded row (l + k - 4) + 4 with l = lw + 8j
            #pragma unroll
            for (int j = 0; j < 5; ++j) {
                ull s2 = s_seq[base + j*(8*CIN)];
                acc[j][0] = fma2(s2, w0, acc[j][0]);
                acc[j][1] = fma2(s2, w1, acc[j][1]);
                acc[j][2] = fma2(s2, w2, acc[j][2]);
                acc[j][3] = fma2(s2, w3, acc[j][3]);
            }
        }
    }

    float4 bias = *(const float4*)(conv_b + f0);
    #pragma unroll
    for (int j = 0; j < 5; ++j) {
        int l = lw + 8*j;
        if (l < LL) {
            float2 v0 = asf2(acc[j][0]); float2 v1 = asf2(acc[j][1]);
            float2 v2 = asf2(acc[j][2]); float2 v3 = asf2(acc[j][3]);
            float4 oA, oB;
            oA.x = fmaxf(v0.x + bias.x, 0.f); oB.x = fmaxf(v0.y + bias.x, 0.f);
            oA.y = fmaxf(v1.x + bias.y, 0.f); oB.y = fmaxf(v1.y + bias.y, 0.f);
            oA.z = fmaxf(v2.x + bias.z, 0.f); oB.z = fmaxf(v2.y + bias.z, 0.f);
            oA.w = fmaxf(v3.x + bias.w, 0.f); oB.w = fmaxf(v3.y + bias.w, 0.f);
            *(float4*)(g_conv + ((size_t)b0*LL + l)*FF + f0)     = oA;
            *(float4*)(g_conv + ((size_t)(b0+1)*LL + l)*FF + f0) = oB;
        }
    }
}

// ---------------------------------------------------------------------------
// Kernel 2: fused post-processing for a batch pair.
//  - yn/yc MLPs evaluated ONLY at positions l=10..24 (all that is consumed)
//  - avg_n = tanh(mean(conv[0:10]) @ navg_w + b)
//  - avg_c = tanh(mean(conv[10+plen : 10+plen+10]) @ cavg_w + b)  (cnt==10 always)
//  - masked neg-max pools + sigmoid head
// ---------------------------------------------------------------------------
#define POST_SMEM (26308*4)

__global__ void __launch_bounds__(256, 2) post_kernel(
    const int*   __restrict__ pep_len,
    const float* __restrict__ n_w1, const float* __restrict__ n_b1,
    const float* __restrict__ n_w2, const float* __restrict__ n_b2,
    const float* __restrict__ c_w1, const float* __restrict__ c_b1,
    const float* __restrict__ c_w2, const float* __restrict__ c_b2,
    const float* __restrict__ navg_w, const float* __restrict__ navg_b,
    const float* __restrict__ cavg_w, const float* __restrict__ cavg_b,
    const float* __restrict__ out_w,  const float* __restrict__ out_b,
    float* __restrict__ out)
{
    extern __shared__ float sm[];
    ull*    s_x    = (ull*)sm;            // 35*128 batch-pair float2
    float*  s_w1n  = sm + 8960;           // 128*64
    float*  s_w1c  = sm + 17152;          // 128*64
    float*  s_w2n  = sm + 25344;          // 64
    float*  s_w2c  = sm + 25408;          // 64
    float*  s_navg = sm + 25472;          // 128
    float*  s_cavg = sm + 25600;          // 128
    float2* s_yn   = (float2*)(sm + 25728); // 15 used
    float2* s_yc   = (float2*)(sm + 25760); // 15 used
    float2* s_redn = (float2*)(sm + 25792); // 128
    float*  s_redc = sm + 26048;            // 256
    float*  s_misc = sm + 26304;            // 4

    const int t  = threadIdx.x;
    const int b0 = blockIdx.x * 2;

    const float* gA = g_conv + (size_t)b0 * (LL*FF);
    const float* gB = gA + LL*FF;
    for (int i = t; i < LL*FF; i += 256)
        ((float2*)s_x)[i] = make_float2(gA[i], gB[i]);
    for (int i = t; i < (FF*HH)/4; i += 256) {
        ((float4*)s_w1n)[i] = ((const float4*)n_w1)[i];
        ((float4*)s_w1c)[i] = ((const float4*)c_w1)[i];
    }
    if (t < 64)              { s_w2n[t] = n_w2[t]; s_w2c[t] = c_w2[t]; }
    if (t >= 64 && t < 192)  { s_navg[t-64] = navg_w[t-64]; s_cavg[t-64] = cavg_w[t-64]; }
    __syncthreads();

    const int lane = t & 31;
    const int w    = t >> 5;

    // ---- Phase A: yn/yc at 15 positions. warp w handles pos w and w+8.
    {
        const int p0 = w;
        const int p1 = w + 8;   // p1==15 computed harmlessly (l=25 in range), not stored
        ull a[2][2][2];         // [pos][net 0=n 1=c][j-half]
        #pragma unroll
        for (int i = 0; i < 2; ++i)
            #pragma unroll
            for (int jn = 0; jn < 2; ++jn)
                #pragma unroll
                for (int jh = 0; jh < 2; ++jh) a[i][jn][jh] = 0ull;

        #pragma unroll 4
        for (int f = 0; f < FF; ++f) {
            ull x0 = s_x[(NFLANK + p0)*FF + f];
            ull x1 = s_x[(NFLANK + p1)*FF + f];
            ull wn0 = splat2(s_w1n[f*HH + lane]);
            ull wn1 = splat2(s_w1n[f*HH + lane + 32]);
            ull wc0 = splat2(s_w1c[f*HH + lane]);
            ull wc1 = splat2(s_w1c[f*HH + lane + 32]);
            a[0][0][0] = fma2(x0, wn0, a[0][0][0]);
            a[0][0][1] = fma2(x0, wn1, a[0][0][1]);
            a[0][1][0] = fma2(x0, wc0, a[0][1][0]);
            a[0][1][1] = fma2(x0, wc1, a[0][1][1]);
            a[1][0][0] = fma2(x1, wn0, a[1][0][0]);
            a[1][0][1] = fma2(x1, wn1, a[1][0][1]);
            a[1][1][0] = fma2(x1, wc0, a[1][1][0]);
            a[1][1][1] = fma2(x1, wc1, a[1][1][1]);
        }

        float bn0 = __ldg(n_b1 + lane), bn1 = __ldg(n_b1 + lane + 32);
        float bc0 = __ldg(c_b1 + lane), bc1 = __ldg(c_b1 + lane + 32);
        float w2n0 = s_w2n[lane], w2n1 = s_w2n[lane + 32];
        float w2c0 = s_w2c[lane], w2c1 = s_w2c[lane + 32];
        float nb2 = __ldg(n_b2), cb2 = __ldg(c_b2);

        #pragma unroll
        for (int pp = 0; pp < 2; ++pp) {
            int p = (pp == 0) ? p0 : p1;
            float2 h0 = asf2(a[pp][0][0]); float2 h1 = asf2(a[pp][0][1]);
            float px = fmaxf(h0.x + bn0, 0.f)*w2n0 + fmaxf(h1.x + bn1, 0.f)*w2n1;
            float py = fmaxf(h0.y + bn0, 0.f)*w2n0 + fmaxf(h1.y + bn1, 0.f)*w2n1;
            float2 g0 = asf2(a[pp][1][0]); float2 g1 = asf2(a[pp][1][1]);
            float qx = fmaxf(g0.x + bc0, 0.f)*w2c0 + fmaxf(g1.x + bc1, 0.f)*w2c1;
            float qy = fmaxf(g0.y + bc0, 0.f)*w2c0 + fmaxf(g1.y + bc1, 0.f)*w2c1;
            #pragma unroll
            for (int o = 16; o > 0; o >>= 1) {
                px += __shfl_xor_sync(0xffffffffu, px, o);
                py += __shfl_xor_sync(0xffffffffu, py, o);
                qx += __shfl_xor_sync(0xffffffffu, qx, o);
                qy += __shfl_xor_sync(0xffffffffu, qy, o);
            }
            if (lane == 0 && p < 15) {
                s_yn[p] = make_float2(tanhf(px + nb2), tanhf(py + nb2));
                s_yc[p] = make_float2(tanhf(qx + cb2), tanhf(qy + cb2));
            }
        }
    }

    // ---- Phase B: avg_n / avg_c partials
    if (t < FF) {
        float sx = 0.f, sy = 0.f;
        #pragma unroll
        for (int l = 0; l < NFLANK; ++l) {
            float2 v = ((float2*)s_x)[l*FF + t];
            sx += v.x; sy += v.y;
        }
        float wv = s_navg[t];
        s_redn[t] = make_float2(sx*0.1f*wv, sy*0.1f*wv);
    }
    {
        int bb = t >> 7;
        int f  = t & 127;
        int pl = __ldg(pep_len + b0 + bb);
        int start = NFLANK + pl;
        float s = 0.f;
        #pragma unroll
        for (int i = 0; i < 10; ++i) {
            float2 v = ((float2*)s_x)[(start + i)*FF + f];
            s += bb ? v.y : v.x;
        }
        s_redc[t] = s*0.1f*s_cavg[f];
    }
    __syncthreads();

    {
        float nb = __ldg(navg_b), cb = __ldg(cavg_b);
        if (w == 0) {
            float2 v0 = s_redn[lane],    v1 = s_redn[lane+32];
            float2 v2 = s_redn[lane+64], v3 = s_redn[lane+96];
            float vx = v0.x+v1.x+v2.x+v3.x;
            float vy = v0.y+v1.y+v2.y+v3.y;
            #pragma unroll
            for (int o = 16; o > 0; o >>= 1) {
                vx += __shfl_xor_sync(0xffffffffu, vx, o);
                vy += __shfl_xor_sync(0xffffffffu, vy, o);
            }
            if (lane == 0) { s_misc[0] = tanhf(vx + nb); s_misc[1] = tanhf(vy + nb); }
        } else if (w == 1 || w == 2) {
            int off = (w == 2) ? 128 : 0;
            float v = s_redc[off+lane] + s_redc[off+lane+32]
                    + s_redc[off+lane+64] + s_redc[off+lane+96];
            #pragma unroll
            for (int o = 16; o > 0; o >>= 1)
                v += __shfl_xor_sync(0xffffffffu, v, o);
            if (lane == 0) s_misc[1 + w] = tanhf(v + cb);   // [2]=batch0, [3]=batch1
        }
    }
    __syncthreads();

    // ---- Phase C: pools + head
    if (t < 2) {
        int b  = b0 + t;
        int pl = __ldg(pep_len + b);
        float cn = t ? s_yn[0].y : s_yn[0].x;
        float mn = 0.f;
        for (int p = 1; p <= pl - 1; ++p) {
            float y = t ? s_yn[p].y : s_yn[p].x;
            mn = fmaxf(mn, y + 1.f);
        }
        float mpn = 1.f - mn;
        float cc = t ? s_yc[pl-1].y : s_yc[pl-1].x;
        float mc = 0.f;
        for (int p = 0; p <= pl - 2; ++p) {
            float y = t ? s_yc[p].y : s_yc[p].x;
            mc = fmaxf(mc, y + 1.f);
        }
        float mpc = 1.f - mc;
        float an = s_misc[t];
        float ac = s_misc[2 + t];
        float comb = cn*__ldg(out_w+0) + mpn*__ldg(out_w+1) + an*__ldg(out_w+2)
                   + cc*__ldg(out_w+3) + mpc*__ldg(out_w+4) + ac*__ldg(out_w+5)
                   + __ldg(out_b);
        out[b] = 1.f / (1.f + expf(-comb));
    }
}

extern "C" void kernel_launch(void* const* d_in, const int* in_sizes, int n_in,
                              void* d_out, int out_size) {
    const float* seq    = (const float*)d_in[0];
    const int*   plen   = (const int*)  d_in[1];
    const float* conv_w = (const float*)d_in[2];
    const float* conv_b = (const float*)d_in[3];
    const float* n_w1   = (const float*)d_in[4];
    const float* n_b1   = (const float*)d_in[5];
    const float* n_w2   = (const float*)d_in[6];
    const float* n_b2   = (const float*)d_in[7];
    const float* c_w1   = (const float*)d_in[8];
    const float* c_b1   = (const float*)d_in[9];
    const float* c_w2   = (const float*)d_in[10];
    const float* c_b2   = (const float*)d_in[11];
    const float* navg_w = (const float*)d_in[12];
    const float* navg_b = (const float*)d_in[13];
    const float* cavg_w = (const float*)d_in[14];
    const float* cavg_b = (const float*)d_in[15];
    const float* out_w  = (const float*)d_in[16];
    const float* out_b  = (const float*)d_in[17];

    cudaFuncSetAttribute(conv_kernel, cudaFuncAttributeMaxDynamicSharedMemorySize, CONV_SMEM);
    cudaFuncSetAttribute(post_kernel, cudaFuncAttributeMaxDynamicSharedMemorySize, POST_SMEM);

    conv_kernel<<<BB/2, 256, CONV_SMEM>>>(seq, conv_w, conv_b);
    post_kernel<<<BB/2, 256, POST_SMEM>>>(plen, n_w1, n_b1, n_w2, n_b2,
                                          c_w1, c_b1, c_w2, c_b2,
                                          navg_w, navg_b, cavg_w, cavg_b,
                                          out_w, out_b, (float*)d_out);
}

// round 3
// speedup vs baseline: 1.3124x; 1.3124x over previous
#include <cuda_runtime.h>
#include <cuda_fp16.h>
#include <cstdint>

#define BB 32768
#define LL 35
#define CIN 21
#define FF 128
#define KK 9
#define HH 64
#define NFLANK 10

#define TILE_M 128
#define KCOLS 192                   // 189 real + 3 zero pad
#define NTILES ((BB*LL)/TILE_M)     // 8960
#define TILES_PER_CTA 4
#define NCTA (NTILES/TILES_PER_CTA) // 2240

// padded strides (fp16 elems) for conflict-free ldmatrix
#define A_STRIDE 200
#define B_STRIDE 136

typedef unsigned long long ull;
typedef uint32_t u32;

// scratch: conv_result [B][L][F] fp32 (587 MB)
__device__ float g_conv[(size_t)BB * LL * FF];

// ---------------------------------------------------------------------------
// helpers
// ---------------------------------------------------------------------------
__device__ __forceinline__ ull fma2(ull a, ull b, ull c) {
    ull d;
    asm("fma.rn.f32x2 %0, %1, %2, %3;" : "=l"(d) : "l"(a), "l"(b), "l"(c));
    return d;
}
__device__ __forceinline__ ull splat2(float x) {
    ull d;
    asm("mov.b64 %0, {%1, %1};" : "=l"(d) : "f"(x));
    return d;
}
__device__ __forceinline__ float2 asf2(ull v) {
    float2 r;
    asm("mov.b64 {%0, %1}, %2;" : "=f"(r.x), "=f"(r.y) : "l"(v));
    return r;
}
__device__ __forceinline__ u32 smem_u32(const void* p) {
    u32 a;
    asm("{ .reg .u64 t; cvta.to.shared.u64 t, %1; cvt.u32.u64 %0, t; }" : "=r"(a) : "l"(p));
    return a;
}
__device__ __forceinline__ void ldmA(u32 addr, u32& r0, u32& r1, u32& r2, u32& r3) {
    asm volatile("ldmatrix.sync.aligned.m8n8.x4.shared.b16 {%0,%1,%2,%3}, [%4];"
                 : "=r"(r0), "=r"(r1), "=r"(r2), "=r"(r3) : "r"(addr));
}
__device__ __forceinline__ void ldmBT(u32 addr, u32& r0, u32& r1, u32& r2, u32& r3) {
    asm volatile("ldmatrix.sync.aligned.m8n8.x4.trans.shared.b16 {%0,%1,%2,%3}, [%4];"
                 : "=r"(r0), "=r"(r1), "=r"(r2), "=r"(r3) : "r"(addr));
}
__device__ __forceinline__ void mma16816(float* d, u32 a0, u32 a1, u32 a2, u32 a3,
                                         u32 b0, u32 b1) {
    asm volatile(
        "mma.sync.aligned.m16n8k16.row.col.f32.f16.f16.f32 "
        "{%0,%1,%2,%3}, {%4,%5,%6,%7}, {%8,%9}, {%0,%1,%2,%3};"
        : "+f"(d[0]), "+f"(d[1]), "+f"(d[2]), "+f"(d[3])
        : "r"(a0), "r"(a1), "r"(a2), "r"(a3), "r"(b0), "r"(b1));
}

// smem layout (bytes)
#define SM_A    0                         // 128*200*2 = 51200
#define SM_B    51200                     // 192*136*2 = 52224
#define SM_SEQ  103424                    // 5*35*21*4 = 14700
#define CONV_SMEM_TOTAL 118144

// ---------------------------------------------------------------------------
// Kernel 1: im2col GEMM on mma.sync (HMMA f16, fp32 accumulate)
// ---------------------------------------------------------------------------
__global__ void __launch_bounds__(256, 1) conv_tc_kernel(
    const float* __restrict__ seq,
    const float* __restrict__ conv_w,
    const float* __restrict__ conv_b)
{
    extern __shared__ char smem[];
    float* s_seq = (float*)(smem + SM_SEQ);
    const u32 s_a = smem_u32(smem) + SM_A;
    const u32 s_b = smem_u32(smem) + SM_B;

    const int t = threadIdx.x;
    const int lane = t & 31;
    const int w = t >> 5;
    const int wr = w >> 1;      // 0..3: row block of 32
    const int wc = w & 1;       // 0..1: col block of 64

    // --- Build B tile once: B[k][n] = conv_w[k*128 + n], fp16, padded stride ---
    for (int idx = t; idx < KCOLS * FF; idx += 256) {
        int k = idx >> 7;
        int n = idx & 127;
        float v = (k < 189) ? __ldg(conv_w + (size_t)k * FF + n) : 0.f;
        *(__half*)(smem + SM_B + (k * B_STRIDE + n) * 2) = __float2half_rn(v);
    }

    // ldmatrix lane addresses
    // A: tile (mt*16 rows, ks*16 cols): addr = row (l&15), col chunk (l>>4)*8
    u32 a_addr[2];
    #pragma unroll
    for (int mt = 0; mt < 2; ++mt)
        a_addr[mt] = s_a + (u32)(((wr * 32 + mt * 16 + (lane & 15)) * A_STRIDE
                                  + (lane >> 4) * 8) * 2);
    // B: tile (ks*16 rows(k), nt2*16 cols(n)): addr = k row (l&15), n chunk (l>>4)*8
    u32 b_addr[4];
    #pragma unroll
    for (int nt2 = 0; nt2 < 4; ++nt2)
        b_addr[nt2] = s_b + (u32)(((lane & 15) * B_STRIDE
                                   + wc * 64 + nt2 * 16 + (lane >> 4) * 8) * 2);

    for (int it = 0; it < TILES_PER_CTA; ++it) {
        const int tile = blockIdx.x * TILES_PER_CTA + it;
        const int r0 = tile * TILE_M;
        const int b_lo = r0 / 35;

        __syncthreads();   // prior tile's ldmatrix reads of s_a / s_seq complete

        // --- stage raw seq for 5-batch window ---
        {
            const size_t gbase = (size_t)b_lo * (LL * CIN);
            const size_t gend = (size_t)BB * (LL * CIN);
            for (int j = t; j < 5 * LL * CIN; j += 256) {
                float v = (gbase + j < gend) ? seq[gbase + j] : 0.f;
                s_seq[j] = v;
            }
        }
        __syncthreads();

        // --- build A tile: 2 threads per row, 48 kc-pairs each ---
        {
            const int row = t >> 1;
            const int half = t & 1;
            const int R = r0 + row;
            const int b = R / 35;
            const int l = R - b * 35;
            const float* sq = s_seq + (b - b_lo) * (LL * CIN);
            #pragma unroll 8
            for (int i = 0; i < 48; ++i) {
                const int kc0 = half * 96 + i * 2;
                const int kc1 = kc0 + 1;
                float v0 = 0.f, v1 = 0.f;
                if (kc0 < 189) {
                    const int k = kc0 / 21, c = kc0 - 21 * k;
                    const int li = l + k - 4;
                    if ((unsigned)li < 35u) v0 = sq[li * 21 + c];
                }
                if (kc1 < 189) {
                    const int k = kc1 / 21, c = kc1 - 21 * k;
                    const int li = l + k - 4;
                    if ((unsigned)li < 35u) v1 = sq[li * 21 + c];
                }
                *(__half2*)(smem + SM_A + (row * A_STRIDE + kc0) * 2) =
                    __floats2half2_rn(v0, v1);
            }
        }
        __syncthreads();

        // --- GEMM: 12 k-steps of 16 ---
        float acc[2][8][4];
        #pragma unroll
        for (int mt = 0; mt < 2; ++mt)
            #pragma unroll
            for (int nt = 0; nt < 8; ++nt)
                #pragma unroll
                for (int q = 0; q < 4; ++q) acc[mt][nt][q] = 0.f;

        #pragma unroll
        for (int ks = 0; ks < 12; ++ks) {
            u32 a[2][4];
            #pragma unroll
            for (int mt = 0; mt < 2; ++mt)
                ldmA(a_addr[mt] + ks * 32, a[mt][0], a[mt][1], a[mt][2], a[mt][3]);
            u32 bf[4][4];
            #pragma unroll
            for (int nt2 = 0; nt2 < 4; ++nt2)
                ldmBT(b_addr[nt2] + ks * (16 * B_STRIDE * 2),
                      bf[nt2][0], bf[nt2][1], bf[nt2][2], bf[nt2][3]);
            #pragma unroll
            for (int mt = 0; mt < 2; ++mt)
                #pragma unroll
                for (int nt = 0; nt < 8; ++nt)
                    mma16816(acc[mt][nt], a[mt][0], a[mt][1], a[mt][2], a[mt][3],
                             bf[nt >> 1][(nt & 1) * 2], bf[nt >> 1][(nt & 1) * 2 + 1]);
        }

        // --- epilogue: bias + relu + fp32 store ---
        {
            const int colbase = wc * 64 + 2 * (lane & 3);
            const int rowbase = r0 + wr * 32 + (lane >> 2);
            #pragma unroll
            for (int nt = 0; nt < 8; ++nt) {
                const int col = colbase + nt * 8;
                const float2 b2 = __ldg((const float2*)(conv_b + col));
                #pragma unroll
                for (int mt = 0; mt < 2; ++mt) {
                    const int row0 = rowbase + mt * 16;
                    float2 o0, o1;
                    o0.x = fmaxf(acc[mt][nt][0] + b2.x, 0.f);
                    o0.y = fmaxf(acc[mt][nt][1] + b2.y, 0.f);
                    o1.x = fmaxf(acc[mt][nt][2] + b2.x, 0.f);
                    o1.y = fmaxf(acc[mt][nt][3] + b2.y, 0.f);
                    *(float2*)(g_conv + (size_t)row0 * FF + col) = o0;
                    *(float2*)(g_conv + (size_t)(row0 + 8) * FF + col) = o1;
                }
            }
        }
    }
}

// ---------------------------------------------------------------------------
// Kernel 2: fused post-processing for a batch pair (unchanged, passing).
// ---------------------------------------------------------------------------
#define POST_SMEM (26308*4)

__global__ void __launch_bounds__(256, 2) post_kernel(
    const int*   __restrict__ pep_len,
    const float* __restrict__ n_w1, const float* __restrict__ n_b1,
    const float* __restrict__ n_w2, const float* __restrict__ n_b2,
    const float* __restrict__ c_w1, const float* __restrict__ c_b1,
    const float* __restrict__ c_w2, const float* __restrict__ c_b2,
    const float* __restrict__ navg_w, const float* __restrict__ navg_b,
    const float* __restrict__ cavg_w, const float* __restrict__ cavg_b,
    const float* __restrict__ out_w,  const float* __restrict__ out_b,
    float* __restrict__ out)
{
    extern __shared__ float sm[];
    ull*    s_x    = (ull*)sm;
    float*  s_w1n  = sm + 8960;
    float*  s_w1c  = sm + 17152;
    float*  s_w2n  = sm + 25344;
    float*  s_w2c  = sm + 25408;
    float*  s_navg = sm + 25472;
    float*  s_cavg = sm + 25600;
    float2* s_yn   = (float2*)(sm + 25728);
    float2* s_yc   = (float2*)(sm + 25760);
    float2* s_redn = (float2*)(sm + 25792);
    float*  s_redc = sm + 26048;
    float*  s_misc = sm + 26304;

    const int t  = threadIdx.x;
    const int b0 = blockIdx.x * 2;

    const float* gA = g_conv + (size_t)b0 * (LL*FF);
    const float* gB = gA + LL*FF;
    for (int i = t; i < LL*FF; i += 256)
        ((float2*)s_x)[i] = make_float2(gA[i], gB[i]);
    for (int i = t; i < (FF*HH)/4; i += 256) {
        ((float4*)s_w1n)[i] = ((const float4*)n_w1)[i];
        ((float4*)s_w1c)[i] = ((const float4*)c_w1)[i];
    }
    if (t < 64)              { s_w2n[t] = n_w2[t]; s_w2c[t] = c_w2[t]; }
    if (t >= 64 && t < 192)  { s_navg[t-64] = navg_w[t-64]; s_cavg[t-64] = cavg_w[t-64]; }
    __syncthreads();

    const int lane = t & 31;
    const int w    = t >> 5;

    {
        const int p0 = w;
        const int p1 = w + 8;
        ull a[2][2][2];
        #pragma unroll
        for (int i = 0; i < 2; ++i)
            #pragma unroll
            for (int jn = 0; jn < 2; ++jn)
                #pragma unroll
                for (int jh = 0; jh < 2; ++jh) a[i][jn][jh] = 0ull;

        #pragma unroll 4
        for (int f = 0; f < FF; ++f) {
            ull x0 = s_x[(NFLANK + p0)*FF + f];
            ull x1 = s_x[(NFLANK + p1)*FF + f];
            ull wn0 = splat2(s_w1n[f*HH + lane]);
            ull wn1 = splat2(s_w1n[f*HH + lane + 32]);
            ull wc0 = splat2(s_w1c[f*HH + lane]);
            ull wc1 = splat2(s_w1c[f*HH + lane + 32]);
            a[0][0][0] = fma2(x0, wn0, a[0][0][0]);
            a[0][0][1] = fma2(x0, wn1, a[0][0][1]);
            a[0][1][0] = fma2(x0, wc0, a[0][1][0]);
            a[0][1][1] = fma2(x0, wc1, a[0][1][1]);
            a[1][0][0] = fma2(x1, wn0, a[1][0][0]);
            a[1][0][1] = fma2(x1, wn1, a[1][0][1]);
            a[1][1][0] = fma2(x1, wc0, a[1][1][0]);
            a[1][1][1] = fma2(x1, wc1, a[1][1][1]);
        }

        float bn0 = __ldg(n_b1 + lane), bn1 = __ldg(n_b1 + lane + 32);
        float bc0 = __ldg(c_b1 + lane), bc1 = __ldg(c_b1 + lane + 32);
        float w2n0 = s_w2n[lane], w2n1 = s_w2n[lane + 32];
        float w2c0 = s_w2c[lane], w2c1 = s_w2c[lane + 32];
        float nb2 = __ldg(n_b2), cb2 = __ldg(c_b2);

        #pragma unroll
        for (int pp = 0; pp < 2; ++pp) {
            int p = (pp == 0) ? p0 : p1;
            float2 h0 = asf2(a[pp][0][0]); float2 h1 = asf2(a[pp][0][1]);
            float px = fmaxf(h0.x + bn0, 0.f)*w2n0 + fmaxf(h1.x + bn1, 0.f)*w2n1;
            float py = fmaxf(h0.y + bn0, 0.f)*w2n0 + fmaxf(h1.y + bn1, 0.f)*w2n1;
            float2 g0 = asf2(a[pp][1][0]); float2 g1 = asf2(a[pp][1][1]);
            float qx = fmaxf(g0.x + bc0, 0.f)*w2c0 + fmaxf(g1.x + bc1, 0.f)*w2c1;
            float qy = fmaxf(g0.y + bc0, 0.f)*w2c0 + fmaxf(g1.y + bc1, 0.f)*w2c1;
            #pragma unroll
            for (int o = 16; o > 0; o >>= 1) {
                px += __shfl_xor_sync(0xffffffffu, px, o);
                py += __shfl_xor_sync(0xffffffffu, py, o);
                qx += __shfl_xor_sync(0xffffffffu, qx, o);
                qy += __shfl_xor_sync(0xffffffffu, qy, o);
            }
            if (lane == 0 && p < 15) {
                s_yn[p] = make_float2(tanhf(px + nb2), tanhf(py + nb2));
                s_yc[p] = make_float2(tanhf(qx + cb2), tanhf(qy + cb2));
            }
        }
    }

    if (t < FF) {
        float sx = 0.f, sy = 0.f;
        #pragma unroll
        for (int l = 0; l < NFLANK; ++l) {
            float2 v = ((float2*)s_x)[l*FF + t];
            sx += v.x; sy += v.y;
        }
        float wv = s_navg[t];
        s_redn[t] = make_float2(sx*0.1f*wv, sy*0.1f*wv);
    }
    {
        int bb = t >> 7;
        int f  = t & 127;
        int pl = __ldg(pep_len + b0 + bb);
        int start = NFLANK + pl;
        float s = 0.f;
        #pragma unroll
        for (int i = 0; i < 10; ++i) {
            float2 v = ((float2*)s_x)[(start + i)*FF + f];
            s += bb ? v.y : v.x;
        }
        s_redc[t] = s*0.1f*s_cavg[f];
    }
    __syncthreads();

    {
        float nb = __ldg(navg_b), cb = __ldg(cavg_b);
        if (w == 0) {
            float2 v0 = s_redn[lane],    v1 = s_redn[lane+32];
            float2 v2 = s_redn[lane+64], v3 = s_redn[lane+96];
            float vx = v0.x+v1.x+v2.x+v3.x;
            float vy = v0.y+v1.y+v2.y+v3.y;
            #pragma unroll
            for (int o = 16; o > 0; o >>= 1) {
                vx += __shfl_xor_sync(0xffffffffu, vx, o);
                vy += __shfl_xor_sync(0xffffffffu, vy, o);
            }
            if (lane == 0) { s_misc[0] = tanhf(vx + nb); s_misc[1] = tanhf(vy + nb); }
        } else if (w == 1 || w == 2) {
            int off = (w == 2) ? 128 : 0;
            float v = s_redc[off+lane] + s_redc[off+lane+32]
                    + s_redc[off+lane+64] + s_redc[off+lane+96];
            #pragma unroll
            for (int o = 16; o > 0; o >>= 1)
                v += __shfl_xor_sync(0xffffffffu, v, o);
            if (lane == 0) s_misc[1 + w] = tanhf(v + cb);
        }
    }
    __syncthreads();

    if (t < 2) {
        int b  = b0 + t;
        int pl = __ldg(pep_len + b);
        float cn = t ? s_yn[0].y : s_yn[0].x;
        float mn = 0.f;
        for (int p = 1; p <= pl - 1; ++p) {
            float y = t ? s_yn[p].y : s_yn[p].x;
            mn = fmaxf(mn, y + 1.f);
        }
        float mpn = 1.f - mn;
        float cc = t ? s_yc[pl-1].y : s_yc[pl-1].x;
        float mc = 0.f;
        for (int p = 0; p <= pl - 2; ++p) {
            float y = t ? s_yc[p].y : s_yc[p].x;
            mc = fmaxf(mc, y + 1.f);
        }
        float mpc = 1.f - mc;
        float an = s_misc[t];
        float ac = s_misc[2 + t];
        float comb = cn*__ldg(out_w+0) + mpn*__ldg(out_w+1) + an*__ldg(out_w+2)
                   + cc*__ldg(out_w+3) + mpc*__ldg(out_w+4) + ac*__ldg(out_w+5)
                   + __ldg(out_b);
        out[b] = 1.f / (1.f + expf(-comb));
    }
}

extern "C" void kernel_launch(void* const* d_in, const int* in_sizes, int n_in,
                              void* d_out, int out_size) {
    const float* seq    = (const float*)d_in[0];
    const int*   plen   = (const int*)  d_in[1];
    const float* conv_w = (const float*)d_in[2];
    const float* conv_b = (const float*)d_in[3];
    const float* n_w1   = (const float*)d_in[4];
    const float* n_b1   = (const float*)d_in[5];
    const float* n_w2   = (const float*)d_in[6];
    const float* n_b2   = (const float*)d_in[7];
    const float* c_w1   = (const float*)d_in[8];
    const float* c_b1   = (const float*)d_in[9];
    const float* c_w2   = (const float*)d_in[10];
    const float* c_b2   = (const float*)d_in[11];
    const float* navg_w = (const float*)d_in[12];
    const float* navg_b = (const float*)d_in[13];
    const float* cavg_w = (const float*)d_in[14];
    const float* cavg_b = (const float*)d_in[15];
    const float* out_w  = (const float*)d_in[16];
    const float* out_b  = (const float*)d_in[17];

    cudaFuncSetAttribute(conv_tc_kernel, cudaFuncAttributeMaxDynamicSharedMemorySize, CONV_SMEM_TOTAL);
    cudaFuncSetAttribute(post_kernel, cudaFuncAttributeMaxDynamicSharedMemorySize, POST_SMEM);

    conv_tc_kernel<<<NCTA, 256, CONV_SMEM_TOTAL>>>(seq, conv_w, conv_b);
    post_kernel<<<BB/2, 256, POST_SMEM>>>(plen, n_w1, n_b1, n_w2, n_b2,
                                          c_w1, c_b1, c_w2, c_b2,
                                          navg_w, navg_b, cavg_w, cavg_b,
                                          out_w, out_b, (float*)d_out);
}

// round 5
// speedup vs baseline: 3.2859x; 2.5037x over previous
#include <cuda_runtime.h>
#include <cuda_fp16.h>
#include <cstdint>

#define BB 32768
#define LL 35
#define CIN 21
#define FF 128
#define HH 64
#define NFLANK 10

#define TILE_M 128
#define NTILES ((BB*LL)/TILE_M)     // 8960
#define TILES_PER_CTA 4
#define NCTA (NTILES/TILES_PER_CTA) // 2240

#define A_STRIDE 200                // f16 elems, conv A tile
#define C_STRIDE 136                // f16 elems, conv-B / conv-out / W1 tiles
#define SEQ_ROW 21
#define SEQ_PB  903                 // (4+35+4)*21 padded rows per batch
#define SEQ_REAL 735                // 35*21

typedef uint32_t u32;

// intermediates: per-position MLP outputs and avg-dot partials
__device__ float g_y[(size_t)BB * LL * 2];    // [R][0]=yn, [1]=yc
__device__ float g_avg[(size_t)BB * LL * 2];  // [R][0]=conv·navg, [1]=conv·cavg

// ---------------------------------------------------------------------------
__device__ __forceinline__ u32 smem_u32(const void* p) {
    u32 a;
    asm("{ .reg .u64 t; cvta.to.shared.u64 t, %1; cvt.u32.u64 %0, t; }" : "=r"(a) : "l"(p));
    return a;
}
__device__ __forceinline__ void ldmA(u32 addr, u32& r0, u32& r1, u32& r2, u32& r3) {
    asm volatile("ldmatrix.sync.aligned.m8n8.x4.shared.b16 {%0,%1,%2,%3}, [%4];"
                 : "=r"(r0), "=r"(r1), "=r"(r2), "=r"(r3) : "r"(addr));
}
__device__ __forceinline__ void ldmBT(u32 addr, u32& r0, u32& r1, u32& r2, u32& r3) {
    asm volatile("ldmatrix.sync.aligned.m8n8.x4.trans.shared.b16 {%0,%1,%2,%3}, [%4];"
                 : "=r"(r0), "=r"(r1), "=r"(r2), "=r"(r3) : "r"(addr));
}
__device__ __forceinline__ void mma16816(float* d, u32 a0, u32 a1, u32 a2, u32 a3,
                                         u32 b0, u32 b1) {
    asm volatile(
        "mma.sync.aligned.m16n8k16.row.col.f32.f16.f16.f32 "
        "{%0,%1,%2,%3}, {%4,%5,%6,%7}, {%8,%9}, {%0,%1,%2,%3};"
        : "+f"(d[0]), "+f"(d[1]), "+f"(d[2]), "+f"(d[3])
        : "r"(a0), "r"(a1), "r"(a2), "r"(a3), "r"(b0), "r"(b1));
}

// smem layout (bytes)
#define SM_A     0                          // 128*200*2 = 51200
#define SM_B     51200                      // 192*136*2 = 52224
#define SM_C     103424                     // 128*136*2 = 34816 (conv out, f16)
#define SM_W1    138240                     // 128*136*2 = 34816 (n_w1|c_w1, f16)
#define SM_SEQ   173056                     // 5*903*4   = 18060
#define SM_AVG   191120                     // 128*4*4   = 2048
#define SM_MISC  193168                     // 512*4     = 2048
#define SMEM_TOTAL 195216

// ---------------------------------------------------------------------------
// Kernel 1: conv GEMM (HMMA) -> f16 tile in smem -> MLP GEMM (HMMA)
//           -> per-row layer2 dot + tanh -> g_y ; per-row avg dots -> g_avg
// ---------------------------------------------------------------------------
__global__ void __launch_bounds__(256, 1) fused_kernel(
    const float* __restrict__ seq,
    const float* __restrict__ conv_w,
    const float* __restrict__ conv_b,
    const float* __restrict__ n_w1, const float* __restrict__ n_b1,
    const float* __restrict__ n_w2, const float* __restrict__ n_b2,
    const float* __restrict__ c_w1, const float* __restrict__ c_b1,
    const float* __restrict__ c_w2, const float* __restrict__ c_b2,
    const float* __restrict__ navg_w,
    const float* __restrict__ cavg_w)
{
    extern __shared__ char smem[];
    float* s_seq  = (float*)(smem + SM_SEQ);
    float* s_avg  = (float*)(smem + SM_AVG);    // [row][net*2+wc]
    float* s_misc = (float*)(smem + SM_MISC);   // [0:128) b1cat [128:256) w2cat [256:384) navg [384:512) cavg
    const u32 s_a  = smem_u32(smem) + SM_A;
    const u32 s_b  = smem_u32(smem) + SM_B;
    const u32 s_c  = smem_u32(smem) + SM_C;
    const u32 s_w1 = smem_u32(smem) + SM_W1;

    const int t = threadIdx.x;
    const int lane = t & 31;
    const int w = t >> 5;
    const int wr = w >> 1;      // 0..3 : 32-row block
    const int wc = w & 1;       // 0..1 : 64-col block / net

    // --- one-time builds ---
    // conv B tile: [k 0..191][n 0..127] f16, stride 136
    for (int idx = t; idx < 192 * FF; idx += 256) {
        int k = idx >> 7, n = idx & 127;
        float v = (k < 189) ? __ldg(conv_w + (size_t)k * FF + n) : 0.f;
        *(__half*)(smem + SM_B + (k * C_STRIDE + n) * 2) = __float2half_rn(v);
    }
    // W1 concat tile: [k 0..127][n 0..127] f16, stride 136
    for (int idx = t; idx < FF * FF; idx += 256) {
        int k = idx >> 7, n = idx & 127;
        float v = (n < 64) ? __ldg(n_w1 + k * HH + n) : __ldg(c_w1 + k * HH + (n - 64));
        *(__half*)(smem + SM_W1 + (k * C_STRIDE + n) * 2) = __float2half_rn(v);
    }
    if (t < 64) {
        s_misc[t]        = __ldg(n_b1 + t);
        s_misc[64 + t]   = __ldg(c_b1 + t);
        s_misc[128 + t]  = __ldg(n_w2 + t);
        s_misc[192 + t]  = __ldg(c_w2 + t);
    }
    if (t < 128) {
        s_misc[256 + t] = __ldg(navg_w + t);
        s_misc[384 + t] = __ldg(cavg_w + t);
    }
    // zero padded seq buffer once (pads persist across tiles)
    for (int j = t; j < 5 * SEQ_PB; j += 256) s_seq[j] = 0.f;

    // ldmatrix lane addresses
    u32 a_addr[2], a2_addr[2];
    #pragma unroll
    for (int mt = 0; mt < 2; ++mt) {
        int r = wr * 32 + mt * 16 + (lane & 15);
        a_addr[mt]  = s_a + (u32)((r * A_STRIDE + (lane >> 4) * 8) * 2);
        a2_addr[mt] = s_c + (u32)((r * C_STRIDE + (lane >> 4) * 8) * 2);
    }
    u32 b_addr[4], b2_addr[4];
    #pragma unroll
    for (int nt2 = 0; nt2 < 4; ++nt2) {
        int cbase = wc * 64 + nt2 * 16 + (lane >> 4) * 8;
        b_addr[nt2]  = s_b  + (u32)(((lane & 15) * C_STRIDE + cbase) * 2);
        b2_addr[nt2] = s_w1 + (u32)(((lane & 15) * C_STRIDE + cbase) * 2);
    }

    const float nb2 = __ldg(n_b2), cb2 = __ldg(c_b2);
    const float b2s = wc ? cb2 : nb2;

    for (int it = 0; it < TILES_PER_CTA; ++it) {
        const int tile = blockIdx.x * TILES_PER_CTA + it;
        const int r0 = tile * TILE_M;
        const int b_lo = r0 / 35;

        __syncthreads();

        // --- stage real seq rows into padded buffer ---
        {
            const size_t gbase = (size_t)b_lo * SEQ_REAL;
            const size_t gend  = (size_t)BB * SEQ_REAL;
            for (int j = t; j < 5 * SEQ_REAL; j += 256) {
                int bi  = j / SEQ_REAL;
                int rem = j - bi * SEQ_REAL;
                float v = (gbase + j < gend) ? seq[gbase + j] : 0.f;
                s_seq[bi * SEQ_PB + 84 + rem] = v;
            }
        }
        __syncthreads();

        // --- build im2col A tile (guard-free inner loop) ---
        {
            const int row = t >> 1, half = t & 1;
            const int R = r0 + row;
            const int b = R / 35;
            const int l = R - b * 35;
            const float* sp = s_seq + (b - b_lo) * SEQ_PB + l * SEQ_ROW;
            #pragma unroll 8
            for (int i = 0; i < 48; ++i) {
                const int kc0 = half * 96 + i * 2;
                float v0 = (kc0 < 189)     ? sp[kc0]     : 0.f;
                float v1 = (kc0 + 1 < 189) ? sp[kc0 + 1] : 0.f;
                *(__half2*)(smem + SM_A + (row * A_STRIDE + kc0) * 2) =
                    __floats2half2_rn(v0, v1);
            }
        }
        __syncthreads();

        // --- conv GEMM: 12 k-steps ---
        float acc[2][8][4];
        #pragma unroll
        for (int mt = 0; mt < 2; ++mt)
            #pragma unroll
            for (int nt = 0; nt < 8; ++nt)
                #pragma unroll
                for (int q = 0; q < 4; ++q) acc[mt][nt][q] = 0.f;

        #pragma unroll
        for (int ks = 0; ks < 12; ++ks) {
            u32 a[2][4];
            #pragma unroll
            for (int mt = 0; mt < 2; ++mt)
                ldmA(a_addr[mt] + ks * 32, a[mt][0], a[mt][1], a[mt][2], a[mt][3]);
            u32 bf[4][4];
            #pragma unroll
            for (int nt2 = 0; nt2 < 4; ++nt2)
                ldmBT(b_addr[nt2] + ks * (16 * C_STRIDE * 2),
                      bf[nt2][0], bf[nt2][1], bf[nt2][2], bf[nt2][3]);
            #pragma unroll
            for (int mt = 0; mt < 2; ++mt)
                #pragma unroll
                for (int nt = 0; nt < 8; ++nt)
                    mma16816(acc[mt][nt], a[mt][0], a[mt][1], a[mt][2], a[mt][3],
                             bf[nt >> 1][(nt & 1) * 2], bf[nt >> 1][(nt & 1) * 2 + 1]);
        }

        // --- epilogue 1: bias+relu -> f16 smem tile; avg-dot partials ---
        {
            float avn[2][2] = {{0.f,0.f},{0.f,0.f}};
            float avc[2][2] = {{0.f,0.f},{0.f,0.f}};
            const int rq = lane >> 2;
            #pragma unroll
            for (int nt = 0; nt < 8; ++nt) {
                const int col = wc * 64 + nt * 8 + 2 * (lane & 3);
                const float2 bb = __ldg((const float2*)(conv_b + col));
                const float nv0 = s_misc[256 + col], nv1 = s_misc[256 + col + 1];
                const float cv0 = s_misc[384 + col], cv1 = s_misc[384 + col + 1];
                #pragma unroll
                for (int mt = 0; mt < 2; ++mt) {
                    const int ra = wr * 32 + mt * 16 + rq;
                    float o0x = fmaxf(acc[mt][nt][0] + bb.x, 0.f);
                    float o0y = fmaxf(acc[mt][nt][1] + bb.y, 0.f);
                    float o1x = fmaxf(acc[mt][nt][2] + bb.x, 0.f);
                    float o1y = fmaxf(acc[mt][nt][3] + bb.y, 0.f);
                    *(__half2*)(smem + SM_C + (ra * C_STRIDE + col) * 2) =
                        __floats2half2_rn(o0x, o0y);
                    *(__half2*)(smem + SM_C + ((ra + 8) * C_STRIDE + col) * 2) =
                        __floats2half2_rn(o1x, o1y);
                    avn[mt][0] += o0x * nv0 + o0y * nv1;
                    avc[mt][0] += o0x * cv0 + o0y * cv1;
                    avn[mt][1] += o1x * nv0 + o1y * nv1;
                    avc[mt][1] += o1x * cv0 + o1y * cv1;
                }
            }
            #pragma unroll
            for (int mt = 0; mt < 2; ++mt)
                #pragma unroll
                for (int h = 0; h < 2; ++h) {
                    float vn = avn[mt][h], vc = avc[mt][h];
                    vn += __shfl_xor_sync(0xffffffffu, vn, 1);
                    vn += __shfl_xor_sync(0xffffffffu, vn, 2);
                    vc += __shfl_xor_sync(0xffffffffu, vc, 1);
                    vc += __shfl_xor_sync(0xffffffffu, vc, 2);
                    if ((lane & 3) == 0) {
                        int row = wr * 32 + mt * 16 + rq + h * 8;
                        s_avg[row * 4 + wc]     = vn;
                        s_avg[row * 4 + 2 + wc] = vc;
                    }
                }
        }
        __syncthreads();

        // combine avg partials -> global
        if (t < 128) {
            const size_t R = (size_t)(r0 + t);
            g_avg[R * 2]     = s_avg[t * 4] + s_avg[t * 4 + 1];
            g_avg[R * 2 + 1] = s_avg[t * 4 + 2] + s_avg[t * 4 + 3];
        }

        // --- MLP GEMM: 8 k-steps over 128 conv features ---
        float acc2[2][8][4];
        #pragma unroll
        for (int mt = 0; mt < 2; ++mt)
            #pragma unroll
            for (int nt = 0; nt < 8; ++nt)
                #pragma unroll
                for (int q = 0; q < 4; ++q) acc2[mt][nt][q] = 0.f;

        #pragma unroll
        for (int ks = 0; ks < 8; ++ks) {
            u32 a[2][4];
            #pragma unroll
            for (int mt = 0; mt < 2; ++mt)
                ldmA(a2_addr[mt] + ks * 32, a[mt][0], a[mt][1], a[mt][2], a[mt][3]);
            u32 bf[4][4];
            #pragma unroll
            for (int nt2 = 0; nt2 < 4; ++nt2)
                ldmBT(b2_addr[nt2] + ks * (16 * C_STRIDE * 2),
                      bf[nt2][0], bf[nt2][1], bf[nt2][2], bf[nt2][3]);
            #pragma unroll
            for (int mt = 0; mt < 2; ++mt)
                #pragma unroll
                for (int nt = 0; nt < 8; ++nt)
                    mma16816(acc2[mt][nt], a[mt][0], a[mt][1], a[mt][2], a[mt][3],
                             bf[nt >> 1][(nt & 1) * 2], bf[nt >> 1][(nt & 1) * 2 + 1]);
        }

        // --- epilogue 2: relu + layer2 dot + tanh -> g_y ---
        {
            float s0[2] = {0.f, 0.f}, s1[2] = {0.f, 0.f};
            #pragma unroll
            for (int nt = 0; nt < 8; ++nt) {
                const int c0 = wc * 64 + nt * 8 + 2 * (lane & 3);
                const float b10 = s_misc[c0], b11 = s_misc[c0 + 1];
                const float w20 = s_misc[128 + c0], w21 = s_misc[128 + c0 + 1];
                #pragma unroll
                for (int mt = 0; mt < 2; ++mt) {
                    s0[mt] += fmaxf(acc2[mt][nt][0] + b10, 0.f) * w20
                            + fmaxf(acc2[mt][nt][1] + b11, 0.f) * w21;
                    s1[mt] += fmaxf(acc2[mt][nt][2] + b10, 0.f) * w20
                            + fmaxf(acc2[mt][nt][3] + b11, 0.f) * w21;
                }
            }
            const int rq = lane >> 2;
            #pragma unroll
            for (int mt = 0; mt < 2; ++mt) {
                float v0 = s0[mt], v1 = s1[mt];
                v0 += __shfl_xor_sync(0xffffffffu, v0, 1);
                v0 += __shfl_xor_sync(0xffffffffu, v0, 2);
                v1 += __shfl_xor_sync(0xffffffffu, v1, 1);
                v1 += __shfl_xor_sync(0xffffffffu, v1, 2);
                if ((lane & 3) == 0) {
                    const int ra = wr * 32 + mt * 16 + rq;
                    g_y[(size_t)(r0 + ra) * 2 + wc]     = tanhf(v0 + b2s);
                    g_y[(size_t)(r0 + ra + 8) * 2 + wc] = tanhf(v1 + b2s);
                }
            }
        }
    }
}

// ---------------------------------------------------------------------------
// Kernel 2: per-batch pools + head
// ---------------------------------------------------------------------------
__global__ void head_kernel(
    const int*   __restrict__ pep_len,
    const float* __restrict__ navg_b,
    const float* __restrict__ cavg_b,
    const float* __restrict__ out_w,
    const float* __restrict__ out_b,
    float* __restrict__ out)
{
    const int b = blockIdx.x * blockDim.x + threadIdx.x;
    if (b >= BB) return;
    const int pl = __ldg(pep_len + b);
    const float* Y = g_y + (size_t)b * LL * 2;
    const float* A = g_avg + (size_t)b * LL * 2;

    const float cn = __ldg(Y + NFLANK * 2);
    float mn = 0.f;
    for (int p = NFLANK + 1; p < NFLANK + pl; ++p)
        mn = fmaxf(mn, __ldg(Y + p * 2) + 1.f);
    const float mpn = 1.f - mn;

    const float cc = __ldg(Y + (NFLANK + pl - 1) * 2 + 1);
    float mc = 0.f;
    for (int p = NFLANK; p < NFLANK + pl - 1; ++p)
        mc = fmaxf(mc, __ldg(Y + p * 2 + 1) + 1.f);
    const float mpc = 1.f - mc;

    float sn = 0.f;
    #pragma unroll
    for (int l = 0; l < NFLANK; ++l) sn += __ldg(A + l * 2);
    const float an = tanhf(sn * 0.1f + __ldg(navg_b));

    const int s0 = NFLANK + pl;
    float sc = 0.f;
    #pragma unroll
    for (int i = 0; i < 10; ++i) sc += __ldg(A + (s0 + i) * 2 + 1);
    const float ac = tanhf(sc * 0.1f + __ldg(cavg_b));

    const float comb = cn * __ldg(out_w + 0) + mpn * __ldg(out_w + 1)
                     + an * __ldg(out_w + 2) + cc * __ldg(out_w + 3)
                     + mpc * __ldg(out_w + 4) + ac * __ldg(out_w + 5)
                     + __ldg(out_b);
    out[b] = 1.f / (1.f + expf(-comb));
}

extern "C" void kernel_launch(void* const* d_in, const int* in_sizes, int n_in,
                              void* d_out, int out_size) {
    const float* seq    = (const float*)d_in[0];
    const int*   plen   = (const int*)  d_in[1];
    const float* conv_w = (const float*)d_in[2];
    const float* conv_b = (const float*)d_in[3];
    const float* n_w1   = (const float*)d_in[4];
    const float* n_b1   = (const float*)d_in[5];
    const float* n_w2   = (const float*)d_in[6];
    const float* n_b2   = (const float*)d_in[7];
    const float* c_w1   = (const float*)d_in[8];
    const float* c_b1   = (const float*)d_in[9];
    const float* c_w2   = (const float*)d_in[10];
    const float* c_b2   = (const float*)d_in[11];
    const float* navg_w = (const float*)d_in[12];
    const float* navg_b = (const float*)d_in[13];
    const float* cavg_w = (const float*)d_in[14];
    const float* cavg_b = (const float*)d_in[15];
    const float* out_w  = (const float*)d_in[16];
    const float* out_b  = (const float*)d_in[17];

    cudaFuncSetAttribute(fused_kernel, cudaFuncAttributeMaxDynamicSharedMemorySize, SMEM_TOTAL);

    fused_kernel<<<NCTA, 256, SMEM_TOTAL>>>(seq, conv_w, conv_b,
                                            n_w1, n_b1, n_w2, n_b2,
                                            c_w1, c_b1, c_w2, c_b2,
                                            navg_w, cavg_w);
    head_kernel<<<(BB + 255) / 256, 256>>>(plen, navg_b, cavg_b, out_w, out_b,
                                           (float*)d_out);
}

// round 7
// speedup vs baseline: 3.9384x; 1.1986x over previous
#include <cuda_runtime.h>
#include <cuda_fp16.h>
#include <cstdint>

#define BB 32768
#define LL 35
#define FF 128
#define HH 64
#define NFLANK 10

#define TILE_M 128
#define NTILES ((BB*LL)/TILE_M)     // 8960
#define TILES_PER_CTA 4
#define NCTA (NTILES/TILES_PER_CTA) // 2240

#define A_STRIDE 200                // f16 elems
#define C_STRIDE 136                // f16 elems
#define SEQ_PB  903                 // (4+35+4)*21 padded floats per batch slot
#define SEQ_REAL 735                // 35*21

typedef uint32_t u32;

// intermediates
__device__ float g_y[(size_t)BB * 15 * 2];    // [b][p=l-10][0]=yn,[1]=yc
__device__ float g_avg[(size_t)BB * LL * 2];  // [b][l][0]=conv·navg,[1]=conv·cavg

// ---------------------------------------------------------------------------
__device__ __forceinline__ u32 smem_u32(const void* p) {
    u32 a;
    asm("{ .reg .u64 t; cvta.to.shared.u64 t, %1; cvt.u32.u64 %0, t; }" : "=r"(a) : "l"(p));
    return a;
}
__device__ __forceinline__ void ldmA(u32 addr, u32& r0, u32& r1, u32& r2, u32& r3) {
    asm volatile("ldmatrix.sync.aligned.m8n8.x4.shared.b16 {%0,%1,%2,%3}, [%4];"
                 : "=r"(r0), "=r"(r1), "=r"(r2), "=r"(r3) : "r"(addr));
}
__device__ __forceinline__ void ldmBT(u32 addr, u32& r0, u32& r1, u32& r2, u32& r3) {
    asm volatile("ldmatrix.sync.aligned.m8n8.x4.trans.shared.b16 {%0,%1,%2,%3}, [%4];"
                 : "=r"(r0), "=r"(r1), "=r"(r2), "=r"(r3) : "r"(addr));
}
__device__ __forceinline__ void mma16816(float* d, u32 a0, u32 a1, u32 a2, u32 a3,
                                         u32 b0, u32 b1) {
    asm volatile(
        "mma.sync.aligned.m16n8k16.row.col.f32.f16.f16.f32 "
        "{%0,%1,%2,%3}, {%4,%5,%6,%7}, {%8,%9}, {%0,%1,%2,%3};"
        : "+f"(d[0]), "+f"(d[1]), "+f"(d[2]), "+f"(d[3])
        : "r"(a0), "r"(a1), "r"(a2), "r"(a3), "r"(b0), "r"(b1));
}

// smem layout (bytes)
#define SM_A     0                    // 128*200*2 = 51200
#define SM_B     51200                // 192*136*2 = 52224
#define SM_C     103424               // 64*136*2  = 17408 (compacted conv rows)
#define SM_W1    120832               // 128*136*2 = 34816
#define SM_SEQ0  155648               // 5*903*4   = 18060
#define SM_SEQ1  173712               // 18060
#define SM_AVG   191776               // 128*4*4   = 2048
#define SM_RED2  193824               // 64*4*4    = 1024
#define SM_MISC  194848               // 512*4     = 2048
#define SMEM_TOTAL 196896

// ---------------------------------------------------------------------------
__device__ __forceinline__ void stage_seq(u32 dstbase, const float* __restrict__ seq,
                                          int b_lo, int t) {
    const size_t gbase = (size_t)b_lo * SEQ_REAL;
    const size_t gend  = (size_t)BB * SEQ_REAL;
    #pragma unroll 1
    for (int j = t; j < 5 * SEQ_REAL; j += 256) {
        int bi  = j / SEQ_REAL;
        int rem = j - bi * SEQ_REAL;
        if (gbase + j < gend) {
            u32 dst = dstbase + (u32)((bi * SEQ_PB + 84 + rem) * 4);
            asm volatile("cp.async.ca.shared.global [%0], [%1], 4;"
                         :: "r"(dst), "l"(seq + gbase + j) : "memory");
        }
    }
    asm volatile("cp.async.commit_group;" ::: "memory");
}
__device__ __forceinline__ void cp_wait0() {
    asm volatile("cp.async.wait_group 0;" ::: "memory");
}

// ---------------------------------------------------------------------------
// Fused kernel: conv GEMM (HMMA) -> compacted f16 tile -> MLP GEMM (M=64)
// ---------------------------------------------------------------------------
__global__ void __launch_bounds__(256, 1) fused_kernel(
    const float* __restrict__ seq,
    const float* __restrict__ conv_w,
    const float* __restrict__ conv_b,
    const float* __restrict__ n_w1, const float* __restrict__ n_b1,
    const float* __restrict__ n_w2, const float* __restrict__ n_b2,
    const float* __restrict__ c_w1, const float* __restrict__ c_b1,
    const float* __restrict__ c_w2, const float* __restrict__ c_b2,
    const float* __restrict__ navg_w,
    const float* __restrict__ cavg_w)
{
    extern __shared__ char smem[];
    float* s_avg  = (float*)(smem + SM_AVG);
    float* s_red2 = (float*)(smem + SM_RED2);
    float* s_misc = (float*)(smem + SM_MISC);
    const u32 sb   = smem_u32(smem);
    const u32 s_a  = sb + SM_A;
    const u32 s_b  = sb + SM_B;
    const u32 s_c  = sb + SM_C;
    const u32 s_w1 = sb + SM_W1;

    const int t = threadIdx.x;
    const int lane = t & 31;
    const int w = t >> 5;
    const int wr = w >> 1, wc = w & 1;      // GEMM1: 4x2 warp grid
    const int wr2 = w & 1, wc2 = w >> 1;    // GEMM2: 2x4 warp grid

    // --- prologue: kick off tile0 seq prefetch first ---
    {
        const int r0_0 = blockIdx.x * TILES_PER_CTA * TILE_M;
        stage_seq(sb + SM_SEQ0, seq, r0_0 / 35, t);
    }
    // zero pad regions of both seq buffers (front/back 84 floats per slot)
    for (int j = t; j < 1680; j += 256) {
        int bufsel = j / 840;
        int r = j - bufsel * 840;
        int bi = r / 168;
        int q = r - bi * 168;
        int idx = (q < 84) ? (bi * SEQ_PB + q) : (bi * SEQ_PB + 819 + (q - 84));
        ((float*)(smem + (bufsel ? SM_SEQ1 : SM_SEQ0)))[idx] = 0.f;
    }
    // conv B tile [k 0..191][n 0..127]
    for (int idx = t; idx < 192 * FF; idx += 256) {
        int k = idx >> 7, n = idx & 127;
        float v = (k < 189) ? __ldg(conv_w + (size_t)k * FF + n) : 0.f;
        *(__half*)(smem + SM_B + (k * C_STRIDE + n) * 2) = __float2half_rn(v);
    }
    // W1 concat [k 0..127][n 0..127]
    for (int idx = t; idx < FF * FF; idx += 256) {
        int k = idx >> 7, n = idx & 127;
        float v = (n < 64) ? __ldg(n_w1 + k * HH + n) : __ldg(c_w1 + k * HH + (n - 64));
        *(__half*)(smem + SM_W1 + (k * C_STRIDE + n) * 2) = __float2half_rn(v);
    }
    if (t < 64) {
        s_misc[t]       = __ldg(n_b1 + t);
        s_misc[64 + t]  = __ldg(c_b1 + t);
        s_misc[128 + t] = __ldg(n_w2 + t);
        s_misc[192 + t] = __ldg(c_w2 + t);
    }
    if (t < 128) {
        s_misc[256 + t] = __ldg(navg_w + t);
        s_misc[384 + t] = __ldg(cavg_w + t);
    }
    const float nb2 = __ldg(n_b2), cb2 = __ldg(c_b2);

    // ldmatrix lane addresses
    u32 a_addr[2], a2_addr[2];
    #pragma unroll
    for (int mt = 0; mt < 2; ++mt) {
        int r1 = wr * 32 + mt * 16 + (lane & 15);
        int r2 = wr2 * 32 + mt * 16 + (lane & 15);
        a_addr[mt]  = s_a + (u32)((r1 * A_STRIDE + (lane >> 4) * 8) * 2);
        a2_addr[mt] = s_c + (u32)((r2 * C_STRIDE + (lane >> 4) * 8) * 2);
    }
    u32 b_addr[4], b2_addr[2];
    #pragma unroll
    for (int nt2 = 0; nt2 < 4; ++nt2) {
        int cbase = wc * 64 + nt2 * 16 + (lane >> 4) * 8;
        b_addr[nt2] = s_b + (u32)(((lane & 15) * C_STRIDE + cbase) * 2);
    }
    #pragma unroll
    for (int nt2 = 0; nt2 < 2; ++nt2) {
        int cbase = wc2 * 32 + nt2 * 16 + (lane >> 4) * 8;
        b2_addr[nt2] = s_w1 + (u32)(((lane & 15) * C_STRIDE + cbase) * 2);
    }

    cp_wait0();
    __syncthreads();

    int buf = 0;
    for (int it = 0; it < TILES_PER_CTA; ++it) {
        const int r0 = (blockIdx.x * TILES_PER_CTA + it) * TILE_M;
        const int b_lo = r0 / 35;
        const int l0r = r0 - b_lo * 35;
        const int c0r = min(max(l0r - 10, 0), 15);
        float* sseq = (float*)(smem + (buf ? SM_SEQ1 : SM_SEQ0));

        // --- build im2col A tile (guard-free reads from padded buffer) ---
        {
            const int row = t >> 1, half = t & 1;
            const int R = r0 + row;
            const int b = R / 35;
            const int l = R - b * 35;
            const float* sp = sseq + (b - b_lo) * SEQ_PB + l * 21;
            #pragma unroll 8
            for (int i = 0; i < 48; ++i) {
                const int kc0 = half * 96 + i * 2;
                float v0 = (kc0 < 189)     ? sp[kc0]     : 0.f;
                float v1 = (kc0 + 1 < 189) ? sp[kc0 + 1] : 0.f;
                *(__half2*)(smem + SM_A + (row * A_STRIDE + kc0) * 2) =
                    __floats2half2_rn(v0, v1);
            }
        }
        __syncthreads();  // sync1: A visible

        // prefetch next tile's seq into the other buffer
        if (it + 1 < TILES_PER_CTA)
            stage_seq(sb + (buf ? SM_SEQ0 : SM_SEQ1), seq, (r0 + TILE_M) / 35, t);

        // --- conv GEMM: 12 k-steps ---
        float acc[2][8][4];
        #pragma unroll
        for (int mt = 0; mt < 2; ++mt)
            #pragma unroll
            for (int nt = 0; nt < 8; ++nt)
                #pragma unroll
                for (int q = 0; q < 4; ++q) acc[mt][nt][q] = 0.f;

        #pragma unroll
        for (int ks = 0; ks < 12; ++ks) {
            u32 a[2][4];
            #pragma unroll
            for (int mt = 0; mt < 2; ++mt)
                ldmA(a_addr[mt] + ks * 32, a[mt][0], a[mt][1], a[mt][2], a[mt][3]);
            u32 bf[4][4];
            #pragma unroll
            for (int nt2 = 0; nt2 < 4; ++nt2)
                ldmBT(b_addr[nt2] + ks * (16 * C_STRIDE * 2),
                      bf[nt2][0], bf[nt2][1], bf[nt2][2], bf[nt2][3]);
            #pragma unroll
            for (int mt = 0; mt < 2; ++mt)
                #pragma unroll
                for (int nt = 0; nt < 8; ++nt)
                    mma16816(acc[mt][nt], a[mt][0], a[mt][1], a[mt][2], a[mt][3],
                             bf[nt >> 1][(nt & 1) * 2], bf[nt >> 1][(nt & 1) * 2 + 1]);
        }

        // --- epilogue 1: bias+relu; compacted f16 store; avg-dot partials ---
        {
            const int rq = lane >> 2;
            int slotc[2][2];
            bool need[2][2];
            #pragma unroll
            for (int mt = 0; mt < 2; ++mt)
                #pragma unroll
                for (int h = 0; h < 2; ++h) {
                    int lr = wr * 32 + mt * 16 + rq + h * 8;
                    int x = l0r + lr;
                    int q = x / 35;
                    int l = x - q * 35;
                    need[mt][h]  = (l >= 10 && l < 25);
                    slotc[mt][h] = q * 15 + (l - 10) - c0r;
                }

            float avn[2][2] = {{0.f,0.f},{0.f,0.f}};
            float avc[2][2] = {{0.f,0.f},{0.f,0.f}};
            #pragma unroll
            for (int nt = 0; nt < 8; ++nt) {
                const int col = wc * 64 + nt * 8 + 2 * (lane & 3);
                const float2 bb = __ldg((const float2*)(conv_b + col));
                const float nv0 = s_misc[256 + col], nv1 = s_misc[256 + col + 1];
                const float cv0 = s_misc[384 + col], cv1 = s_misc[384 + col + 1];
                #pragma unroll
                for (int mt = 0; mt < 2; ++mt) {
                    float o0x = fmaxf(acc[mt][nt][0] + bb.x, 0.f);
                    float o0y = fmaxf(acc[mt][nt][1] + bb.y, 0.f);
                    float o1x = fmaxf(acc[mt][nt][2] + bb.x, 0.f);
                    float o1y = fmaxf(acc[mt][nt][3] + bb.y, 0.f);
                    if (need[mt][0])
                        *(__half2*)(smem + SM_C + (slotc[mt][0] * C_STRIDE + col) * 2) =
                            __floats2half2_rn(o0x, o0y);
                    if (need[mt][1])
                        *(__half2*)(smem + SM_C + (slotc[mt][1] * C_STRIDE + col) * 2) =
                            __floats2half2_rn(o1x, o1y);
                    avn[mt][0] += o0x * nv0 + o0y * nv1;
                    avc[mt][0] += o0x * cv0 + o0y * cv1;
                    avn[mt][1] += o1x * nv0 + o1y * nv1;
                    avc[mt][1] += o1x * cv0 + o1y * cv1;
                }
            }
            #pragma unroll
            for (int mt = 0; mt < 2; ++mt)
                #pragma unroll
                for (int h = 0; h < 2; ++h) {
                    float vn = avn[mt][h], vc = avc[mt][h];
                    vn += __shfl_xor_sync(0xffffffffu, vn, 1);
                    vn += __shfl_xor_sync(0xffffffffu, vn, 2);
                    vc += __shfl_xor_sync(0xffffffffu, vc, 1);
                    vc += __shfl_xor_sync(0xffffffffu, vc, 2);
                    if ((lane & 3) == 0) {
                        int row = wr * 32 + mt * 16 + rq + h * 8;
                        s_avg[row * 4 + wc]     = vn;
                        s_avg[row * 4 + 2 + wc] = vc;
                    }
                }
        }
        __syncthreads();  // sync2: C + avg partials visible

        // combine avg partials -> global
        if (t < 128) {
            const size_t R = (size_t)(r0 + t);
            g_avg[R * 2]     = s_avg[t * 4] + s_avg[t * 4 + 1];
            g_avg[R * 2 + 1] = s_avg[t * 4 + 2] + s_avg[t * 4 + 3];
        }

        // --- MLP GEMM: M=64 (compacted rows), N=128, K=128 ---
        float acc2[2][4][4];
        #pragma unroll
        for (int mt = 0; mt < 2; ++mt)
            #pragma unroll
            for (int nt = 0; nt < 4; ++nt)
                #pragma unroll
                for (int q = 0; q < 4; ++q) acc2[mt][nt][q] = 0.f;

        #pragma unroll
        for (int ks = 0; ks < 8; ++ks) {
            u32 a[2][4];
            #pragma unroll
            for (int mt = 0; mt < 2; ++mt)
                ldmA(a2_addr[mt] + ks * 32, a[mt][0], a[mt][1], a[mt][2], a[mt][3]);
            u32 bf[2][4];
            #pragma unroll
            for (int nt2 = 0; nt2 < 2; ++nt2)
                ldmBT(b2_addr[nt2] + ks * (16 * C_STRIDE * 2),
                      bf[nt2][0], bf[nt2][1], bf[nt2][2], bf[nt2][3]);
            #pragma unroll
            for (int mt = 0; mt < 2; ++mt)
                #pragma unroll
                for (int nt = 0; nt < 4; ++nt)
                    mma16816(acc2[mt][nt], a[mt][0], a[mt][1], a[mt][2], a[mt][3],
                             bf[nt >> 1][(nt & 1) * 2], bf[nt >> 1][(nt & 1) * 2 + 1]);
        }

        // --- epilogue 2: relu + layer2 partial dot -> s_red2 ---
        {
            float p0[2] = {0.f, 0.f}, p1[2] = {0.f, 0.f};
            #pragma unroll
            for (int nt = 0; nt < 4; ++nt) {
                const int c0 = wc2 * 32 + nt * 8 + 2 * (lane & 3);
                const float b10 = s_misc[c0], b11 = s_misc[c0 + 1];
                const float w20 = s_misc[128 + c0], w21 = s_misc[128 + c0 + 1];
                #pragma unroll
                for (int mt = 0; mt < 2; ++mt) {
                    p0[mt] += fmaxf(acc2[mt][nt][0] + b10, 0.f) * w20
                            + fmaxf(acc2[mt][nt][1] + b11, 0.f) * w21;
                    p1[mt] += fmaxf(acc2[mt][nt][2] + b10, 0.f) * w20
                            + fmaxf(acc2[mt][nt][3] + b11, 0.f) * w21;
                }
            }
            const int rq = lane >> 2;
            #pragma unroll
            for (int mt = 0; mt < 2; ++mt) {
                float v0 = p0[mt], v1 = p1[mt];
                v0 += __shfl_xor_sync(0xffffffffu, v0, 1);
                v0 += __shfl_xor_sync(0xffffffffu, v0, 2);
                v1 += __shfl_xor_sync(0xffffffffu, v1, 1);
                v1 += __shfl_xor_sync(0xffffffffu, v1, 2);
                if ((lane & 3) == 0) {
                    const int row0 = wr2 * 32 + mt * 16 + rq;
                    s_red2[row0 * 4 + wc2]       = v0;
                    s_red2[(row0 + 8) * 4 + wc2] = v1;
                }
            }
        }
        __syncthreads();  // sync3: red2 visible

        // final combine -> g_y (compact layout)
        if (t < 64) {
            float pn = s_red2[t * 4] + s_red2[t * 4 + 1];
            float pc = s_red2[t * 4 + 2] + s_red2[t * 4 + 3];
            int idx = t + b_lo * 15 + c0r;    // global needed-row index
            int batch = idx / 15;
            int p = idx - batch * 15;
            int R = batch * 35 + 10 + p;
            if (R >= r0 && R < r0 + TILE_M) {
                g_y[(size_t)batch * 30 + p * 2]     = tanhf(pn + nb2);
                g_y[(size_t)batch * 30 + p * 2 + 1] = tanhf(pc + cb2);
            }
        }

        cp_wait0();
        __syncthreads();  // sync4: next seq buffer ready; red2 reads done
        buf ^= 1;
    }
}

// ---------------------------------------------------------------------------
// head: pools + sigmoid
// ---------------------------------------------------------------------------
__global__ void head_kernel(
    const int*   __restrict__ pep_len,
    const float* __restrict__ navg_b,
    const float* __restrict__ cavg_b,
    const float* __restrict__ out_w,
    const float* __restrict__ out_b,
    float* __restrict__ out)
{
    const int b = blockIdx.x * blockDim.x + threadIdx.x;
    if (b >= BB) return;
    const int pl = __ldg(pep_len + b);
    const float* Y = g_y + (size_t)b * 30;        // [p][2], p = l-10
    const float* A = g_avg + (size_t)b * LL * 2;

    const float cn = __ldg(Y + 0);
    float mn = 0.f;
    for (int p = 1; p <= pl - 1; ++p)
        mn = fmaxf(mn, __ldg(Y + p * 2) + 1.f);
    const float mpn = 1.f - mn;

    const float cc = __ldg(Y + (pl - 1) * 2 + 1);
    float mc = 0.f;
    for (int p = 0; p <= pl - 2; ++p)
        mc = fmaxf(mc, __ldg(Y + p * 2 + 1) + 1.f);
    const float mpc = 1.f - mc;

    float sn = 0.f;
    #pragma unroll
    for (int l = 0; l < NFLANK; ++l) sn += __ldg(A + l * 2);
    const float an = tanhf(sn * 0.1f + __ldg(navg_b));

    const int s0 = NFLANK + pl;
    float sc = 0.f;
    #pragma unroll
    for (int i = 0; i < 10; ++i) sc += __ldg(A + (s0 + i) * 2 + 1);
    const float ac = tanhf(sc * 0.1f + __ldg(cavg_b));

    const float comb = cn * __ldg(out_w + 0) + mpn * __ldg(out_w + 1)
                     + an * __ldg(out_w + 2) + cc * __ldg(out_w + 3)
                     + mpc * __ldg(out_w + 4) + ac * __ldg(out_w + 5)
                     + __ldg(out_b);
    out[b] = 1.f / (1.f + expf(-comb));
}

extern "C" void kernel_launch(void* const* d_in, const int* in_sizes, int n_in,
                              void* d_out, int out_size) {
    const float* seq    = (const float*)d_in[0];
    const int*   plen   = (const int*)  d_in[1];
    const float* conv_w = (const float*)d_in[2];
    const float* conv_b = (const float*)d_in[3];
    const float* n_w1   = (const float*)d_in[4];
    const float* n_b1   = (const float*)d_in[5];
    const float* n_w2   = (const float*)d_in[6];
    const float* n_b2   = (const float*)d_in[7];
    const float* c_w1   = (const float*)d_in[8];
    const float* c_b1   = (const float*)d_in[9];
    const float* c_w2   = (const float*)d_in[10];
    const float* c_b2   = (const float*)d_in[11];
    const float* navg_w = (const float*)d_in[12];
    const float* navg_b = (const float*)d_in[13];
    const float* cavg_w = (const float*)d_in[14];
    const float* cavg_b = (const float*)d_in[15];
    const float* out_w  = (const float*)d_in[16];
    const float* out_b  = (const float*)d_in[17];

    cudaFuncSetAttribute(fused_kernel, cudaFuncAttributeMaxDynamicSharedMemorySize, SMEM_TOTAL);

    fused_kernel<<<NCTA, 256, SMEM_TOTAL>>>(seq, conv_w, conv_b,
                                            n_w1, n_b1, n_w2, n_b2,
                                            c_w1, c_b1, c_w2, c_b2,
                                            navg_w, cavg_w);
    head_kernel<<<(BB + 255) / 256, 256>>>(plen, navg_b, cavg_b, out_w, out_b,
                                           (float*)d_out);
}